// round 12
// baseline (speedup 1.0000x reference)
#include <cuda_runtime.h>

// entmax-1.5 attention, B=8 H=8 S=1024 D=64, fp32.
// Prepass: Q,K -> bf16 hi/lo planes; V -> transposed Vt[d][k] hi/lo planes.
// Main: QT=16, 256 thr, 2 CTAs/SM, cp.async double-buffered tiles,
// mma.sync.m16n8k16 with 3-term hi/lo split, Newton entmax.

#define SEQ  1024
#define DH   64
#define QT   16
#define NTHR 256
#define PS   1036        // S row stride (u32 words)
#define NEWTON 10

typedef unsigned int u32;

// smem word offsets
#define S_W   0
#define KB_W  16576      // 2 buffers x (2 planes x 64 rows x 36 w) = 9216 w
#define QP_W  25792      // 2 planes x 16 rows x 36 w = 1152 w
#define TOT_W 26944
#define SMEM_BYTES (TOT_W * 4)   // 107776

// device scratch: bf16 planes, 8MB each
__device__ uint4 g_QH[524288], g_QL[524288];
__device__ uint4 g_KH[524288], g_KL[524288];
__device__ uint4 g_VTH[524288], g_VTL[524288];

__device__ __forceinline__ u32 prmt(u32 a, u32 b, u32 s) {
    u32 d; asm("prmt.b32 %0, %1, %2, %3;" : "=r"(d) : "r"(a), "r"(b), "r"(s)); return d;
}
__device__ __forceinline__ u32 cvt2(float hi, float lo) {
    u32 d; asm("cvt.rn.bf16x2.f32 %0, %1, %2;" : "=r"(d) : "f"(hi), "f"(lo)); return d;
}
__device__ __forceinline__ u32 pack1(float x) {             // {lo16 | hi-bf16}
    u32 Hp = cvt2(x, x);
    float h = __uint_as_float(Hp << 16);
    u32 Lp = cvt2(0.f, x - h);
    return prmt(Hp, Lp, 0x5410);
}
__device__ __forceinline__ void mma16816(float* c, const u32* a, u32 b0, u32 b1) {
    asm volatile("mma.sync.aligned.m16n8k16.row.col.f32.bf16.bf16.f32 "
        "{%0,%1,%2,%3}, {%4,%5,%6,%7}, {%8,%9}, {%0,%1,%2,%3};"
        : "+f"(c[0]), "+f"(c[1]), "+f"(c[2]), "+f"(c[3])
        : "r"(a[0]), "r"(a[1]), "r"(a[2]), "r"(a[3]), "r"(b0), "r"(b1));
}
__device__ __forceinline__ void ldmx4(u32 addr, u32* r) {
    asm volatile("ldmatrix.sync.aligned.m8n8.x4.shared.b16 {%0,%1,%2,%3}, [%4];"
        : "=r"(r[0]), "=r"(r[1]), "=r"(r[2]), "=r"(r[3]) : "r"(addr));
}
__device__ __forceinline__ void ldmx2(u32 addr, u32* r) {
    asm volatile("ldmatrix.sync.aligned.m8n8.x2.shared.b16 {%0,%1}, [%2];"
        : "=r"(r[0]), "=r"(r[1]) : "r"(addr));
}
// A frag (16 rows g/g+8) hi+lo from packed P
__device__ __forceinline__ void ldA(const u32* p, u32* ah, u32* al) {
    uint2 w;
    w = *(const uint2*)(p);
    ah[0] = prmt(w.x, w.y, 0x5410); al[0] = prmt(w.x, w.y, 0x7632);
    w = *(const uint2*)(p + 8 * PS);
    ah[1] = prmt(w.x, w.y, 0x5410); al[1] = prmt(w.x, w.y, 0x7632);
    w = *(const uint2*)(p + 8);
    ah[2] = prmt(w.x, w.y, 0x5410); al[2] = prmt(w.x, w.y, 0x7632);
    w = *(const uint2*)(p + 8 * PS + 8);
    ah[3] = prmt(w.x, w.y, 0x5410); al[3] = prmt(w.x, w.y, 0x7632);
}
__device__ __forceinline__ u32 s2u(const void* p) {
    u32 a;
    asm("{ .reg .u64 t; cvta.to.shared.u64 t, %1; cvt.u32.u64 %0, t; }" : "=r"(a) : "l"(p));
    return a;
}
__device__ __forceinline__ void cp16(u32 dst, const void* src) {
    asm volatile("cp.async.ca.shared.global [%0], [%1], 16;"
                 :: "r"(dst), "l"(__cvta_generic_to_global(src)));
}
#define CP_COMMIT() asm volatile("cp.async.commit_group;" ::: "memory")
#define CP_WAIT0()  asm volatile("cp.async.wait_group 0;" ::: "memory")

// ===================== prepass: Q,K -> hi/lo planes ========================
__global__ void __launch_bounds__(512) prepQK(const float4* __restrict__ q,
                                              const float4* __restrict__ k)
{
    int i = blockIdx.x * 512 + threadIdx.x;
    float4 f = q[i];
    u32 h0 = cvt2(f.y, f.x), h1 = cvt2(f.w, f.z);
    u32 l0 = cvt2(f.y - __uint_as_float(h0 & 0xffff0000u),
                  f.x - __uint_as_float(h0 << 16));
    u32 l1 = cvt2(f.w - __uint_as_float(h1 & 0xffff0000u),
                  f.z - __uint_as_float(h1 << 16));
    ((uint2*)g_QH)[i] = make_uint2(h0, h1);
    ((uint2*)g_QL)[i] = make_uint2(l0, l1);
    f = k[i];
    h0 = cvt2(f.y, f.x); h1 = cvt2(f.w, f.z);
    l0 = cvt2(f.y - __uint_as_float(h0 & 0xffff0000u),
              f.x - __uint_as_float(h0 << 16));
    l1 = cvt2(f.w - __uint_as_float(h1 & 0xffff0000u),
              f.z - __uint_as_float(h1 << 16));
    ((uint2*)g_KH)[i] = make_uint2(h0, h1);
    ((uint2*)g_KL)[i] = make_uint2(l0, l1);
}

// ===================== prepass: V -> transposed hi/lo planes ===============
__global__ void __launch_bounds__(256) prepV(const float* __restrict__ v)
{
    int bh = blockIdx.x, kb = blockIdx.y;
    int d = threadIdx.x & 63, kg = threadIdx.x >> 6;
    const float* Vb = v + bh * 65536;
#pragma unroll
    for (int c = 0; c < 4; c++) {
        int k0 = kb * 128 + c * 32 + kg * 8;
        float x[8];
#pragma unroll
        for (int j = 0; j < 8; j++) x[j] = Vb[(k0 + j) * 64 + d];
        u32 h[4], l[4];
#pragma unroll
        for (int p = 0; p < 4; p++) {
            h[p] = cvt2(x[2*p+1], x[2*p]);
            l[p] = cvt2(x[2*p+1] - __uint_as_float(h[p] & 0xffff0000u),
                        x[2*p]   - __uint_as_float(h[p] << 16));
        }
        int base = (bh * 65536 + d * 1024 + k0) >> 3;
        g_VTH[base] = make_uint4(h[0], h[1], h[2], h[3]);
        g_VTL[base] = make_uint4(l[0], l[1], l[2], l[3]);
    }
}

// =========================== main kernel ===================================
__global__ void __launch_bounds__(NTHR, 2)
attn_entmax15_p(float* __restrict__ og)
{
    extern __shared__ u32 sm[];
    float* Sf = (float*)sm;
    u32*   Sw = sm;

    const int tid  = threadIdx.x;
    const int lane = tid & 31;
    const int wid  = tid >> 5;        // 0..7
    const int g    = lane >> 2;
    const int t    = lane & 3;
    const int qt   = blockIdx.x;      // 0..63
    const int bh   = blockIdx.y;      // 0..63

    float* Og = og + (size_t)bh * SEQ * DH + (size_t)qt * QT * DH;

    const u32 smb = s2u(sm);

    // ---- async stage Q planes (1 cp16 per thread) + K tile 0 ----
    {
        int pl = tid >> 7, rem = tid & 127, row = rem >> 3, seg = rem & 7;
        const uint4* src = (pl ? g_QL : g_QH) + bh * 8192 + (qt * 16 + row) * 8 + seg;
        cp16(smb + (QP_W + pl * 576 + row * 36 + seg * 4) * 4, src);
    }
#pragma unroll
    for (int i = 0; i < 2; i++) {     // K tile 0: 1024 chunks / 256 thr, planes split
        int idx = i * NTHR + tid;     // 0..511 : plane = idx>>8? No: 64 rows x 8 seg = 512 per plane
        int row = idx >> 3, seg = idx & 7;
        cp16(smb + (KB_W + 0 * 4608 + 0 * 2304 + row * 36 + seg * 4) * 4,
             g_KH + bh * 8192 + row * 8 + seg);
        cp16(smb + (KB_W + 0 * 4608 + 1 * 2304 + row * 36 + seg * 4) * 4,
             g_KL + bh * 8192 + row * 8 + seg);
    }
    CP_COMMIT();
    CP_WAIT0();
    __syncthreads();

    // ---- hoist Q fragments (all 4 ksteps, hi+lo) ----
    const u32 QHB = smb + QP_W * 4;
    const u32 QLB = QHB + 2304;
    const int aAdr = (lane & 15) * 144 + (lane >> 4) * 16;
    u32 qh[4][4], ql[4][4];
#pragma unroll
    for (int ks = 0; ks < 4; ks++) {
        ldmx4(QHB + aAdr + ks * 32, qh[ks]);
        ldmx4(QLB + aAdr + ks * 32, ql[ks]);
    }

    // ======================= GEMM1: S = Q K^T (16 tiles of 64 keys) ========
    const int bAdr = (wid * 8 + (lane & 7)) * 144 + ((lane >> 3) & 1) * 16;
    for (int kt = 0; kt < 16; kt++) {
        const int buf = kt & 1;
        if (kt) { CP_WAIT0(); __syncthreads(); }
        if (kt < 15) {                 // prefetch kt+1 into other buffer
            const int nb = buf ^ 1;
#pragma unroll
            for (int i = 0; i < 2; i++) {
                int idx = i * NTHR + tid;
                int row = idx >> 3, seg = idx & 7;
                int gi = bh * 8192 + ((kt + 1) * 64 + row) * 8 + seg;
                cp16(smb + (KB_W + nb * 4608 + row * 36 + seg * 4) * 4, g_KH + gi);
                cp16(smb + (KB_W + nb * 4608 + 2304 + row * 36 + seg * 4) * 4, g_KL + gi);
            }
            CP_COMMIT();
        }
        const u32 KHB = smb + (KB_W + buf * 4608) * 4;
        const u32 KLB = KHB + 9216;

        float c[4] = {0.f, 0.f, 0.f, 0.f};
#pragma unroll
        for (int ks = 0; ks < 4; ks++) {
            u32 b2h[2], b2l[2];
            ldmx2(KHB + bAdr + ks * 32, b2h);
            ldmx2(KLB + bAdr + ks * 32, b2l);
            mma16816(c, qh[ks], b2h[0], b2h[1]);
            mma16816(c, qh[ks], b2l[0], b2l[1]);
            mma16816(c, ql[ks], b2h[0], b2h[1]);
        }
        const int col = kt * 64 + wid * 8 + 2 * t;
        *(float2*)&Sf[g * PS + col]       = make_float2(c[0], c[1]);
        *(float2*)&Sf[(g + 8) * PS + col] = make_float2(c[2], c[3]);
    }
    __syncthreads();

    // ---- prefetch V tile 0 (hidden under entmax) ----
#pragma unroll
    for (int i = 0; i < 2; i++) {
        int idx = i * NTHR + tid;
        int row = idx >> 3, seg = idx & 7;     // row = d
        int gi = bh * 8192 + row * 128 + seg;  // vt = 0
        cp16(smb + (KB_W + row * 36 + seg * 4) * 4, g_VTH + gi);
        cp16(smb + (KB_W + 2304 + row * 36 + seg * 4) * 4, g_VTL + gi);
    }
    CP_COMMIT();

    // ======================= entmax-1.5 (Newton) ============================
    {
        const int row0 = wid * 2;
        for (int rr = 0; rr < 2; rr++) {
            const int row = row0 + rr;
            float x[32];
            float m = -1e30f;
#pragma unroll
            for (int j = 0; j < 32; j++) {
                x[j] = Sf[row * PS + j * 32 + lane] * 0.0625f;
                m = fmaxf(m, x[j]);
            }
#pragma unroll
            for (int o = 16; o; o >>= 1) m = fmaxf(m, __shfl_xor_sync(0xffffffffu, m, o));
#pragma unroll
            for (int j = 0; j < 32; j++) x[j] -= m;

            float tau = -1.0f;
#pragma unroll 1
            for (int it = 0; it < NEWTON; it++) {
                float s = 0.f, r = 0.f;
#pragma unroll
                for (int j = 0; j < 32; j++) {
                    float u = fmaxf(x[j] - tau, 0.f);
                    s = fmaf(u, u, s);
                    r += u;
                }
#pragma unroll
                for (int o = 16; o; o >>= 1) {
                    s += __shfl_xor_sync(0xffffffffu, s, o);
                    r += __shfl_xor_sync(0xffffffffu, r, o);
                }
                tau += (s - 1.0f) / (2.0f * r);
            }
#pragma unroll
            for (int j = 0; j < 32; j++) {
                float u = fmaxf(x[j] - tau, 0.f);
                Sw[row * PS + j * 32 + lane] = pack1(u * u);
            }
        }
    }

    // ======================= GEMM2: O = P V (16 tiles of 64 keys) ===========
    // warp wid owns d columns [wid*8, wid*8+8)
    const int vAdr = (wid * 8 + (lane & 7)) * 144 + ((lane >> 3) & 1) * 16;
    float oc[4] = {0.f, 0.f, 0.f, 0.f};

    for (int vt = 0; vt < 16; vt++) {
        const int buf = vt & 1;
        CP_WAIT0();
        __syncthreads();
        if (vt < 15) {
            const int nb = buf ^ 1;
#pragma unroll
            for (int i = 0; i < 2; i++) {
                int idx = i * NTHR + tid;
                int row = idx >> 3, seg = idx & 7;
                int gi = bh * 8192 + row * 128 + (vt + 1) * 8 + seg;
                cp16(smb + (KB_W + nb * 4608 + row * 36 + seg * 4) * 4, g_VTH + gi);
                cp16(smb + (KB_W + nb * 4608 + 2304 + row * 36 + seg * 4) * 4, g_VTL + gi);
            }
            CP_COMMIT();
        }
        const u32 VHB = smb + (KB_W + buf * 4608) * 4;
        const u32 VLB = VHB + 9216;

#pragma unroll
        for (int ksl = 0; ksl < 4; ksl++) {
            const int kw = vt * 64 + ksl * 16 + 2 * t;
            u32 ah[4], al[4];
            ldA(Sw + g * PS + kw, ah, al);
            u32 b2h[2], b2l[2];
            ldmx2(VHB + vAdr + ksl * 32, b2h);
            ldmx2(VLB + vAdr + ksl * 32, b2l);
            mma16816(oc, ah, b2h[0], b2h[1]);
            mma16816(oc, ah, b2l[0], b2l[1]);
            mma16816(oc, al, b2h[0], b2h[1]);
        }
    }

    // ---- write O directly (warp owns distinct d-slice; no reduction) ----
    {
        const int d = wid * 8 + 2 * t;
        *(float2*)&Og[g * DH + d]       = make_float2(oc[0], oc[1]);
        *(float2*)&Og[(g + 8) * DH + d] = make_float2(oc[2], oc[3]);
    }
}

extern "C" void kernel_launch(void* const* d_in, const int* in_sizes, int n_in,
                              void* d_out, int out_size)
{
    const float* q = (const float*)d_in[0];
    const float* k = (const float*)d_in[1];
    const float* v = (const float*)d_in[2];
    float* out = (float*)d_out;

    cudaFuncSetAttribute(attn_entmax15_p,
                         cudaFuncAttributeMaxDynamicSharedMemorySize, SMEM_BYTES);

    prepQK<<<2048, 512>>>((const float4*)q, (const float4*)k);
    prepV<<<dim3(64, 8), 256>>>(v);
    dim3 grid(SEQ / QT, 8 * 8);   // (64 q-tiles, 64 bh)
    attn_entmax15_p<<<grid, NTHR, SMEM_BYTES>>>(out);
}

// round 14
// speedup vs baseline: 1.1016x; 1.1016x over previous
#include <cuda_runtime.h>

#define NTHR 256
#define NEWTON 8
typedef unsigned int u32;
typedef unsigned long long u64;

#define Q_W    0          // 2 planes x 16 x 36 w
#define K_W    1152       // 2 buf x 9216 w (K 128x36x2pl / Vt 64x68x2pl)
#define O_W    19584      // 16 x 68 f32
#define RED_W  20672      // 512 w reduction slots
#define TOT_W  21184
#define SMEM_BYTES (TOT_W * 4)   // 84736

__device__ uint4 g_QH[524288], g_QL[524288];
__device__ uint4 g_KH[524288], g_KL[524288];
__device__ uint4 g_VTH[524288], g_VTL[524288];

__device__ __forceinline__ u32 cvt2(float hi, float lo) {
    u32 d; asm("cvt.rn.bf16x2.f32 %0, %1, %2;" : "=r"(d) : "f"(hi), "f"(lo)); return d;
}
__device__ __forceinline__ u64 pk64(float lo, float hi) {
    u64 d; asm("mov.b64 %0, {%1, %2};" : "=l"(d) : "f"(lo), "f"(hi)); return d;
}
__device__ __forceinline__ u64 dup2(float v) {
    u64 d; asm("mov.b64 %0, {%1, %1};" : "=l"(d) : "f"(v)); return d;
}
__device__ __forceinline__ u64 add2(u64 a, u64 b) {
    u64 d; asm("add.rn.f32x2 %0, %1, %2;" : "=l"(d) : "l"(a), "l"(b)); return d;
}
__device__ __forceinline__ u64 mul2(u64 a, u64 b) {
    u64 d; asm("mul.rn.f32x2 %0, %1, %2;" : "=l"(d) : "l"(a), "l"(b)); return d;
}
__device__ __forceinline__ u64 fma2(u64 a, u64 b, u64 c) {
    u64 d; asm("fma.rn.f32x2 %0, %1, %2, %3;" : "=l"(d) : "l"(a), "l"(b), "l"(c)); return d;
}
__device__ __forceinline__ void mma16816(float* c, const u32* a, u32 b0, u32 b1) {
    asm volatile("mma.sync.aligned.m16n8k16.row.col.f32.bf16.bf16.f32 "
        "{%0,%1,%2,%3}, {%4,%5,%6,%7}, {%8,%9}, {%0,%1,%2,%3};"
        : "+f"(c[0]), "+f"(c[1]), "+f"(c[2]), "+f"(c[3])
        : "r"(a[0]), "r"(a[1]), "r"(a[2]), "r"(a[3]), "r"(b0), "r"(b1));
}
__device__ __forceinline__ void mma1688(float* c, u32 a0, u32 a1, u32 b0) {
    asm volatile("mma.sync.aligned.m16n8k8.row.col.f32.bf16.bf16.f32 "
        "{%0,%1,%2,%3}, {%4,%5}, {%6}, {%0,%1,%2,%3};"
        : "+f"(c[0]), "+f"(c[1]), "+f"(c[2]), "+f"(c[3])
        : "r"(a0), "r"(a1), "r"(b0));
}
__device__ __forceinline__ void ldmx4(u32 addr, u32* r) {
    asm volatile("ldmatrix.sync.aligned.m8n8.x4.shared.b16 {%0,%1,%2,%3}, [%4];"
        : "=r"(r[0]), "=r"(r[1]), "=r"(r[2]), "=r"(r[3]) : "r"(addr));
}
__device__ __forceinline__ void ldmx2(u32 addr, u32* r) {
    asm volatile("ldmatrix.sync.aligned.m8n8.x2.shared.b16 {%0,%1}, [%2];"
        : "=r"(r[0]), "=r"(r[1]) : "r"(addr));
}
__device__ __forceinline__ u32 s2u(const void* p) {
    u32 a;
    asm("{ .reg .u64 t; cvta.to.shared.u64 t, %1; cvt.u32.u64 %0, t; }" : "=r"(a) : "l"(p));
    return a;
}
__device__ __forceinline__ void cp16(u32 dst, const void* src) {
    asm volatile("cp.async.ca.shared.global [%0], [%1], 16;"
                 :: "r"(dst), "l"(__cvta_generic_to_global(src)));
}
#define CP_COMMIT() asm volatile("cp.async.commit_group;" ::: "memory")
#define CP_WAIT(n)  asm volatile("cp.async.wait_group " #n ";" ::: "memory")

__global__ void __launch_bounds__(512) prepQK(const float4* __restrict__ q,
                                              const float4* __restrict__ k)
{
    int i = blockIdx.x * 512 + threadIdx.x;
    float4 f = q[i];
    f.x *= 0.0625f; f.y *= 0.0625f; f.z *= 0.0625f; f.w *= 0.0625f;
    u32 h0 = cvt2(f.y, f.x), h1 = cvt2(f.w, f.z);
    u32 l0 = cvt2(f.y - __uint_as_float(h0 & 0xffff0000u),
                  f.x - __uint_as_float(h0 << 16));
    u32 l1 = cvt2(f.w - __uint_as_float(h1 & 0xffff0000u),
                  f.z - __uint_as_float(h1 << 16));
    ((uint2*)g_QH)[i] = make_uint2(h0, h1);
    ((uint2*)g_QL)[i] = make_uint2(l0, l1);
    f = k[i];
    h0 = cvt2(f.y, f.x); h1 = cvt2(f.w, f.z);
    l0 = cvt2(f.y - __uint_as_float(h0 & 0xffff0000u),
              f.x - __uint_as_float(h0 << 16));
    l1 = cvt2(f.w - __uint_as_float(h1 & 0xffff0000u),
              f.z - __uint_as_float(h1 << 16));
    ((uint2*)g_KH)[i] = make_uint2(h0, h1);
    ((uint2*)g_KL)[i] = make_uint2(l0, l1);
}

__global__ void __launch_bounds__(256) prepV(const float* __restrict__ v)
{
    int bh = blockIdx.x, kb = blockIdx.y;
    int d = threadIdx.x & 63, kg = threadIdx.x >> 6;
    const float* Vb = v + bh * 65536;
#pragma unroll
    for (int c = 0; c < 4; c++) {
        int k0 = kb * 128 + c * 32 + kg * 8;
        float x[8];
#pragma unroll
        for (int j = 0; j < 8; j++) x[j] = Vb[(k0 + j) * 64 + d] * 0.25f;
        u32 h[4], l[4];
#pragma unroll
        for (int p = 0; p < 4; p++) {
            h[p] = cvt2(x[2*p+1], x[2*p]);
            l[p] = cvt2(x[2*p+1] - __uint_as_float(h[p] & 0xffff0000u),
                        x[2*p]   - __uint_as_float(h[p] << 16));
        }
        int base = bh * 8192 + d * 128 + (k0 >> 3);
        g_VTH[base] = make_uint4(h[0], h[1], h[2], h[3]);
        g_VTL[base] = make_uint4(l[0], l[1], l[2], l[3]);
    }
}

__global__ void __launch_bounds__(NTHR, 2)
attn_regP(float* __restrict__ og)
{
    extern __shared__ u32 sm[];
    float* smf = (float*)sm;
    const int tid  = threadIdx.x;
    const int lane = tid & 31;
    const int wid  = tid >> 5;
    const int g    = lane >> 2;
    const int tq   = lane & 3;
    const int qt   = blockIdx.x;
    const int bh   = blockIdx.y;
    float* Og = og + (size_t)bh * 65536 + (size_t)qt * 1024;
    const u32 smb = s2u(sm);

    for (int i = tid; i < 16 * 68; i += NTHR) smf[O_W + i] = 0.f;

    {   // Q planes (256 cp16) + K chunk 0
        int pl = tid >> 7, rem = tid & 127, row = rem >> 3, seg = rem & 7;
        cp16(smb + (Q_W + pl * 576 + row * 36 + seg * 4) * 4,
             (pl ? g_QL : g_QH) + (size_t)bh * 8192 + (qt * 16 + row) * 8 + seg);
    }
#pragma unroll
    for (int i = 0; i < 4; i++) {
        int idx = i * NTHR + tid, row = idx >> 3, seg = idx & 7;
        int gi = bh * 8192 + row * 8 + seg;
        cp16(smb + (K_W + row * 36 + seg * 4) * 4, g_KH + gi);
        cp16(smb + (K_W + 4608 + row * 36 + seg * 4) * 4, g_KL + gi);
    }
    CP_COMMIT();
    CP_WAIT(0);
    __syncthreads();

    const u32 QHB = smb + Q_W * 4, QLB = QHB + 2304;
    const int aAdr = (lane & 15) * 144 + (lane >> 4) * 16;
    u32 qh[4][4], ql[4][4];
#pragma unroll
    for (int ks = 0; ks < 4; ks++) {
        ldmx4(QHB + aAdr + ks * 32, qh[ks]);
        ldmx4(QLB + aAdr + ks * 32, ql[ks]);
    }

    // ===== GEMM1: 8 chunks x 2 tiles; C stays in registers =====
    float cc[16][4];
#pragma unroll 1
    for (int c = 0; c < 8; c++) {
        const int buf = c & 1;
        if (c < 7) {
            const int nb = buf ^ 1;
#pragma unroll
            for (int i = 0; i < 4; i++) {
                int idx = i * NTHR + tid, row = idx >> 3, seg = idx & 7;
                int gi = bh * 8192 + ((c + 1) * 128 + row) * 8 + seg;
                cp16(smb + (K_W + nb * 9216 + row * 36 + seg * 4) * 4, g_KH + gi);
                cp16(smb + (K_W + nb * 9216 + 4608 + row * 36 + seg * 4) * 4, g_KL + gi);
            }
            CP_COMMIT();
            CP_WAIT(1);
        } else {
            CP_WAIT(0);
        }
        __syncthreads();
        const u32 KHB = smb + (K_W + buf * 9216) * 4;
#pragma unroll
        for (int tl = 0; tl < 2; tl++) {
            float* c4 = cc[2 * c + tl];
            c4[0] = c4[1] = c4[2] = c4[3] = 0.f;
            const u32 bA = KHB + (16 * wid + tl * 8 + (lane & 7)) * 144
                         + ((lane >> 3) & 1) * 16;
#pragma unroll
            for (int ks = 0; ks < 4; ks++) {
                u32 b2h[2], b2l[2];
                ldmx2(bA + ks * 32, b2h);
                ldmx2(bA + 18432 + ks * 32, b2l);
                mma16816(c4, qh[ks], b2h[0], b2h[1]);
                mma16816(c4, qh[ks], b2l[0], b2l[1]);
                mma16816(c4, ql[ks], b2h[0], b2h[1]);
            }
        }
        __syncthreads();
    }

    // prefetch V chunk 0 (hidden under entmax)
#pragma unroll
    for (int i = 0; i < 4; i++) {
        int idx = i * NTHR + tid, d = idx >> 4, s = idx & 15;
        int gi = bh * 8192 + d * 128 + s;
        cp16(smb + (K_W + d * 68 + s * 4) * 4, g_VTH + gi);
        cp16(smb + (K_W + 4608 + d * 68 + s * 4) * 4, g_VTL + gi);
    }
    CP_COMMIT();

    // ===== entmax-1.5 Newton, in registers (rows g and g+8) =====
    float mg = -1e30f, mh = -1e30f;
#pragma unroll
    for (int T = 0; T < 16; T++) {
        mg = fmaxf(mg, fmaxf(cc[T][0], cc[T][1]));
        mh = fmaxf(mh, fmaxf(cc[T][2], cc[T][3]));
    }
    mg = fmaxf(mg, __shfl_xor_sync(~0u, mg, 1));
    mg = fmaxf(mg, __shfl_xor_sync(~0u, mg, 2));
    mh = fmaxf(mh, __shfl_xor_sync(~0u, mh, 1));
    mh = fmaxf(mh, __shfl_xor_sync(~0u, mh, 2));
    if (tq == 0) {
        smf[RED_W + (32 + g) * 8 + wid] = mg;
        smf[RED_W + (40 + g) * 8 + wid] = mh;
    }
    __syncthreads();
    float Mg = -1e30f, Mh = -1e30f;
#pragma unroll
    for (int w = 0; w < 8; w++) {
        Mg = fmaxf(Mg, smf[RED_W + (32 + g) * 8 + w]);
        Mh = fmaxf(Mh, smf[RED_W + (40 + g) * 8 + w]);
    }
    float taug = Mg - 1.f, tauh = Mh - 1.f;

    u64 xg[16], xh[16];
#pragma unroll
    for (int T = 0; T < 16; T++) {
        xg[T] = pk64(cc[T][0], cc[T][1]);
        xh[T] = pk64(cc[T][2], cc[T][3]);
    }
    const u64 ABS2 = 0x7fffffff7fffffffULL;
#pragma unroll 1
    for (int it = 0; it < NEWTON; it++) {
        const int p = it & 1;
        u64 ntg = dup2(-taug), nth = dup2(-tauh);
        u64 s2g = 0, r2g = 0, s2h = 0, r2h = 0;
#pragma unroll
        for (int T = 0; T < 16; T++) {
            u64 tg = add2(xg[T], ntg);
            u64 ug = add2(tg, tg & ABS2);        // 2*max(t,0)
            s2g = fma2(ug, ug, s2g); r2g = add2(r2g, ug);
            u64 th = add2(xh[T], nth);
            u64 uh = add2(th, th & ABS2);
            s2h = fma2(uh, uh, s2h); r2h = add2(r2h, uh);
        }
        float2 v2;
        v2 = *(float2*)&s2g; float fsg = v2.x + v2.y;
        v2 = *(float2*)&r2g; float frg = v2.x + v2.y;
        v2 = *(float2*)&s2h; float fsh = v2.x + v2.y;
        v2 = *(float2*)&r2h; float frh = v2.x + v2.y;
        fsg += __shfl_xor_sync(~0u, fsg, 1); fsg += __shfl_xor_sync(~0u, fsg, 2);
        frg += __shfl_xor_sync(~0u, frg, 1); frg += __shfl_xor_sync(~0u, frg, 2);
        fsh += __shfl_xor_sync(~0u, fsh, 1); fsh += __shfl_xor_sync(~0u, fsh, 2);
        frh += __shfl_xor_sync(~0u, frh, 1); frh += __shfl_xor_sync(~0u, frh, 2);
        if (tq == 0) {
            smf[RED_W + (p * 32 + g) * 8 + wid]      = fsg;
            smf[RED_W + (p * 32 + 16 + g) * 8 + wid] = frg;
            smf[RED_W + (p * 32 + 8 + g) * 8 + wid]  = fsh;
            smf[RED_W + (p * 32 + 24 + g) * 8 + wid] = frh;
        }
        __syncthreads();
        float S = 0.f, R = 0.f, Sh = 0.f, Rh = 0.f;
#pragma unroll
        for (int w = 0; w < 8; w++) {
            S  += smf[RED_W + (p * 32 + g) * 8 + w];
            R  += smf[RED_W + (p * 32 + 16 + g) * 8 + w];
            Sh += smf[RED_W + (p * 32 + 8 + g) * 8 + w];
            Rh += smf[RED_W + (p * 32 + 24 + g) * 8 + w];
        }
        taug += __fdividef(S - 4.f, 4.f * R);     // s2 counts 4u^2
        tauh += __fdividef(Sh - 4.f, 4.f * Rh);
    }
    const u64 ntgF = dup2(-taug), nthF = dup2(-tauh);

    // ===== GEMM2: O = P V, P frags straight from registers =====
    float oc[8][4];
#pragma unroll
    for (int dt = 0; dt < 8; dt++)
        oc[dt][0] = oc[dt][1] = oc[dt][2] = oc[dt][3] = 0.f;

#pragma unroll 1
    for (int c = 0; c < 8; c++) {
        const int buf = c & 1;
        if (c < 7) {
            const int nb = buf ^ 1;
#pragma unroll
            for (int i = 0; i < 4; i++) {
                int idx = i * NTHR + tid, d = idx >> 4, s = idx & 15;
                int gi = bh * 8192 + d * 128 + (c + 1) * 16 + s;
                cp16(smb + (K_W + nb * 9216 + d * 68 + s * 4) * 4, g_VTH + gi);
                cp16(smb + (K_W + nb * 9216 + 4608 + d * 68 + s * 4) * 4, g_VTL + gi);
            }
            CP_COMMIT();
            CP_WAIT(1);
        } else {
            CP_WAIT(0);
        }
        __syncthreads();
        const u32 VHB = smb + (K_W + buf * 9216) * 4;
#pragma unroll
        for (int kk = 0; kk < 2; kk++) {
            const int T = 2 * c + kk;
            u64 tg = add2(xg[T], ntgF);
            u64 ug = add2(tg, tg & ABS2);
            u64 Pg = mul2(ug, ug);                 // 4p (V carries the /4)
            u64 th = add2(xh[T], nthF);
            u64 uh = add2(th, th & ABS2);
            u64 Ph = mul2(uh, uh);
            float2 pg = *(float2*)&Pg, ph = *(float2*)&Ph;
            u32 a0h = cvt2(pg.y, pg.x);
            u32 a1h = cvt2(ph.y, ph.x);
            u32 a0l = cvt2(pg.y - __uint_as_float(a0h & 0xffff0000u),
                           pg.x - __uint_as_float(a0h << 16));
            u32 a1l = cvt2(ph.y - __uint_as_float(a1h & 0xffff0000u),
                           ph.x - __uint_as_float(a1h << 16));
            const u32 vA = VHB + lane * 272 + (16 * wid + kk * 8) * 2;
            u32 b0h[4], b1h[4], b0l[4], b1l[4];
            ldmx4(vA, b0h);
            ldmx4(vA + 8704, b1h);
            ldmx4(vA + 18432, b0l);
            ldmx4(vA + 18432 + 8704, b1l);
#pragma unroll
            for (int dt = 0; dt < 4; dt++) {
                mma1688(oc[dt],     a0h, a1h, b0h[dt]);
                mma1688(oc[dt],     a0h, a1h, b0l[dt]);
                mma1688(oc[dt],     a0l, a1l, b0h[dt]);
                mma1688(oc[dt + 4], a0h, a1h, b1h[dt]);
                mma1688(oc[dt + 4], a0h, a1h, b1l[dt]);
                mma1688(oc[dt + 4], a0l, a1l, b1h[dt]);
            }
        }
        __syncthreads();
    }

    // ===== k-split reduction + output =====
#pragma unroll
    for (int dt = 0; dt < 8; dt++) {
        int col = dt * 8 + 2 * tq;
        atomicAdd(&smf[O_W + g * 68 + col],           oc[dt][0]);
        atomicAdd(&smf[O_W + g * 68 + col + 1],       oc[dt][1]);
        atomicAdd(&smf[O_W + (g + 8) * 68 + col],     oc[dt][2]);
        atomicAdd(&smf[O_W + (g + 8) * 68 + col + 1], oc[dt][3]);
    }
    __syncthreads();
#pragma unroll
    for (int i = 0; i < 4; i++) {
        int idx = i * NTHR + tid;
        int q = idx >> 6, d = idx & 63;
        Og[idx] = smf[O_W + q * 68 + d];
    }
}

extern "C" void kernel_launch(void* const* d_in, const int* in_sizes, int n_in,
                              void* d_out, int out_size)
{
    const float* q = (const float*)d_in[0];
    const float* k = (const float*)d_in[1];
    const float* v = (const float*)d_in[2];
    float* out = (float*)d_out;

    cudaFuncSetAttribute(attn_regP,
                         cudaFuncAttributeMaxDynamicSharedMemorySize, SMEM_BYTES);

    prepQK<<<2048, 512>>>((const float4*)q, (const float4*)k);
    prepV<<<dim3(64, 8), 256>>>(v);
    dim3 grid(64, 64);
    attn_regP<<<grid, NTHR, SMEM_BYTES>>>(out);
}